// round 1
// baseline (speedup 1.0000x reference)
#include <cuda_runtime.h>

// Two double accumulators in device-global scratch (no allocation allowed).
// g_acc[0] = sum of squared translation diffs, g_acc[1] = sum of squared
// wrapped rotation diffs.
__device__ double g_acc[2];

__global__ void wmse_zero_kernel() {
    g_acc[0] = 0.0;
    g_acc[1] = 0.0;
}

__device__ __forceinline__ float wrap_angle(float a) {
    const float PI  = 3.14159265358979323846f;
    const float TPI = 6.28318530717958647692f;
    a = (a >  PI) ? a - TPI : a;
    a = (a < -PI) ? a + TPI : a;
    return a;
}

__global__ void wmse_reduce_kernel(const float4* __restrict__ p4,
                                   const float4* __restrict__ t4,
                                   long long n4) {
    float ts = 0.0f;  // translation squared-diff sum
    float rs = 0.0f;  // rotation squared-diff sum (wrapped)

    const long long stride = (long long)gridDim.x * blockDim.x;
    for (long long v = (long long)blockIdx.x * blockDim.x + threadIdx.x;
         v < n4; v += stride) {
        float4 p = p4[v];
        float4 t = t4[v];

        // First channel of this float4: c0 = (4*v) % 6 = {0,4,2} for v%3 = {0,1,2}
        int m  = (int)(v % 3);
        int c0 = (m == 1) ? 4 : ((m == 2) ? 2 : 0);

        float pe[4] = {p.x, p.y, p.z, p.w};
        float te[4] = {t.x, t.y, t.z, t.w};

        #pragma unroll
        for (int j = 0; j < 4; j++) {
            int c = c0 + j;
            if (c >= 6) c -= 6;
            bool is_rot = (c >= 3);

            float d   = pe[j] - te[j];
            float dw  = wrap_angle(pe[j]) - wrap_angle(te[j]);
            float d2  = d * d;
            float dw2 = dw * dw;

            ts += is_rot ? 0.0f : d2;
            rs += is_rot ? dw2  : 0.0f;
        }
    }

    // Warp reduction
    #pragma unroll
    for (int o = 16; o > 0; o >>= 1) {
        ts += __shfl_xor_sync(0xffffffffu, ts, o);
        rs += __shfl_xor_sync(0xffffffffu, rs, o);
    }

    __shared__ float sts[32];
    __shared__ float srs[32];
    int lane = threadIdx.x & 31;
    int warp = threadIdx.x >> 5;
    if (lane == 0) { sts[warp] = ts; srs[warp] = rs; }
    __syncthreads();

    if (warp == 0) {
        int nw = blockDim.x >> 5;
        ts = (lane < nw) ? sts[lane] : 0.0f;
        rs = (lane < nw) ? srs[lane] : 0.0f;
        #pragma unroll
        for (int o = 16; o > 0; o >>= 1) {
            ts += __shfl_xor_sync(0xffffffffu, ts, o);
            rs += __shfl_xor_sync(0xffffffffu, rs, o);
        }
        if (lane == 0) {
            atomicAdd(&g_acc[0], (double)ts);
            atomicAdd(&g_acc[1], (double)rs);
        }
    }
}

__global__ void wmse_finalize_kernel(float* __restrict__ out, long long n) {
    // n total elements per tensor; half are translation, half rotation.
    double cnt = (double)(n / 2);
    double trans_loss = g_acc[0] / cnt;           // TRANS_WEIGHT = 1.0
    double rot_loss   = (g_acc[1] / cnt) * 100.0; // ROT_WEIGHT = 100.0
    out[0] = (float)(trans_loss + rot_loss);
    out[1] = (float)trans_loss;
    out[2] = (float)rot_loss;
}

extern "C" void kernel_launch(void* const* d_in, const int* in_sizes, int n_in,
                              void* d_out, int out_size) {
    const float4* pred4   = (const float4*)d_in[0];
    const float4* target4 = (const float4*)d_in[1];
    long long n  = (long long)in_sizes[0];
    long long n4 = n / 4;

    wmse_zero_kernel<<<1, 1>>>();

    const int threads = 256;
    const int blocks  = 1184;  // ~8 CTAs per SM (148 SMs on sm_100a-class part)
    wmse_reduce_kernel<<<blocks, threads>>>(pred4, target4, n4);

    wmse_finalize_kernel<<<1, 1>>>((float*)d_out, n);
}